// round 8
// baseline (speedup 1.0000x reference)
#include <cuda_runtime.h>
#include <cstdint>

#define PP     8       // personas
#define FF     64      // factor dim
#define SB     200     // items per batch row
#define TPB    192
#define VPITCH 272     // 17 x 16B: odd pitch -> conflict-free LDS.128
#define U_OFF  (SB * VPITCH)        // 54400
#define SMEMB  (U_OFF + PP*FF*4)    // 56448 B -> 4 CTAs/SM

typedef unsigned long long ull;

__device__ __forceinline__ ull fma2(ull a, ull b, ull c) {
    ull d; asm("fma.rn.f32x2 %0, %1, %2, %3;" : "=l"(d) : "l"(a), "l"(b), "l"(c)); return d;
}
__device__ __forceinline__ void lds16(ull& a, ull& b, uint32_t addr) {
    asm volatile("ld.shared.v2.b64 {%0,%1}, [%2];" : "=l"(a), "=l"(b) : "r"(addr));
}
__device__ __forceinline__ float hsum2(ull a) {
    return __uint_as_float((unsigned)a) + __uint_as_float((unsigned)(a >> 32));
}
__device__ __forceinline__ void cp16(uint32_t dst, const void* src) {
    asm volatile("cp.async.cg.shared.global [%0], [%1], 16;" :: "r"(dst), "l"(src) : "memory");
}
__device__ __forceinline__ void mbar_wait(uint32_t addr) {
    asm volatile(
        "{\n\t"
        ".reg .pred P;\n\t"
        "LAB_%=:\n\t"
        "mbarrier.try_wait.parity.acquire.cta.shared::cta.b64 P, [%0], 0, 0x989680;\n\t"
        "@!P bra LAB_%=;\n\t"
        "}\n\t"
        :: "r"(addr) : "memory");
}

__global__ __launch_bounds__(TPB, 4) void cf_kernel(
    const int*   __restrict__ user,     // [B]
    const int*   __restrict__ items,    // [B,SB]
    const float* __restrict__ ufac,     // [N_USERS, PP, FF]
    const float* __restrict__ ifac,     // [N_ITEMS, FF]
    float*       __restrict__ pred,     // [B,SB]
    float*       __restrict__ scores)   // [B,SB,PP]
{
    extern __shared__ __align__(16) char smem[];
    __shared__ ull mbar;

    const int tid = threadIdx.x;
    const long long b = blockIdx.x;

    const uint32_t sv = (uint32_t)__cvta_generic_to_shared(smem);
    const uint32_t su = sv + U_OFF;
    const uint32_t mb = (uint32_t)__cvta_generic_to_shared(&mbar);

    if (tid == 0)
        asm volatile("mbarrier.init.shared.b64 [%0], %1;" :: "r"(mb), "r"(TPB) : "memory");
    __syncthreads();

    // ---- Async gather: v = 200 rows x 16 chunks of 16B (16 lanes/row, coalesced) ----
    const int* idxp = items + b * SB;
    const float* ubp = ufac + (long long)__ldg(&user[b]) * (PP * FF);
    #pragma unroll
    for (int k = 0; k < 17; k++) {
        const int i = tid + k * TPB;
        if (i < SB * 16) {
            const int r = i >> 4;
            const int c = i & 15;
            const int idx = __ldg(idxp + r);
            cp16(sv + (uint32_t)(r * VPITCH + c * 16),
                 ifac + (long long)idx * FF + (c << 2));
        }
    }
    if (tid < 128) cp16(su + (uint32_t)(tid * 16), ubp + tid * 4);
    asm volatile("cp.async.mbarrier.arrive.noinc.shared::cta.b64 [%0];" :: "r"(mb) : "memory");

    // ---- Compute: pair (2k,2k+1) shares rows {k,k+50,k+100,k+150}; each does 4 personas ----
    if (tid < 100) {
        mbar_wait(mb);

        const int pair = tid >> 1;   // 0..49
        const int half = tid & 1;    // persona half
        uint32_t va[4];
        #pragma unroll
        for (int h = 0; h < 4; h++)
            va[h] = sv + (uint32_t)((pair + 50 * h) * VPITCH);
        const uint32_t ua = su + (uint32_t)(half * 4 * 256);

        ull acc[4][4];
        #pragma unroll
        for (int h = 0; h < 4; h++)
            #pragma unroll
            for (int p = 0; p < 4; p++) acc[h][p] = 0ull;

        #pragma unroll
        for (int cc = 0; cc < FF / 4; cc++) {
            ull vx[4], vy[4];
            #pragma unroll
            for (int h = 0; h < 4; h++)
                lds16(vx[h], vy[h], va[h] + cc * 16);   // pair lanes same addr -> merged
            #pragma unroll
            for (int p = 0; p < 4; p++) {
                ull ux, uy;
                lds16(ux, uy, ua + p * 256 + cc * 16);  // broadcast (2 addrs/warp)
                #pragma unroll
                for (int h = 0; h < 4; h++) {
                    acc[h][p] = fma2(vx[h], ux, acc[h][p]);
                    acc[h][p] = fma2(vy[h], uy, acc[h][p]);
                }
            }
        }

        const unsigned msk = __activemask();
        #pragma unroll
        for (int h = 0; h < 4; h++) {
            float mine[4];
            #pragma unroll
            for (int p = 0; p < 4; p++) mine[p] = hsum2(acc[h][p]);

            float oth[4];
            #pragma unroll
            for (int p = 0; p < 4; p++) oth[p] = __shfl_xor_sync(msk, mine[p], 1);

            float r[PP];
            #pragma unroll
            for (int p = 0; p < 4; p++) {
                r[half * 4 + p]       = mine[p];
                r[(1 - half) * 4 + p] = oth[p];
            }

            float m = r[0];
            #pragma unroll
            for (int p = 1; p < PP; p++) m = fmaxf(m, r[p]);
            float e[PP], sum = 0.f;
            #pragma unroll
            for (int p = 0; p < PP; p++) { e[p] = __expf(r[p] - m); sum += e[p]; }
            const float inv = 1.f / sum;

            float a[PP], pr = 0.f;
            #pragma unroll
            for (int p = 0; p < PP; p++) { a[p] = e[p] * inv; pr = fmaf(a[p], r[p], pr); }

            const int s = pair + 50 * h;
            const long long g = b * SB + s;
            if (half == 0) pred[g] = pr;
            *(float4*)(scores + g * (long long)PP + half * 4) =
                make_float4(a[half * 4], a[half * 4 + 1], a[half * 4 + 2], a[half * 4 + 3]);
        }
    }
}

extern "C" void kernel_launch(void* const* d_in, const int* in_sizes, int n_in,
                              void* d_out, int out_size) {
    const int*   user  = (const int*)d_in[0];
    const int*   items = (const int*)d_in[1];
    const float* ufac  = (const float*)d_in[2];
    const float* ifac  = (const float*)d_in[3];

    const int B = in_sizes[0];

    float* out    = (float*)d_out;
    float* pred   = out;                        // [B,SB]
    float* scores = out + (long long)B * SB;    // [B,SB,PP]

    cudaFuncSetAttribute(cf_kernel, cudaFuncAttributeMaxDynamicSharedMemorySize, SMEMB);

    cf_kernel<<<B, TPB, SMEMB>>>(user, items, ufac, ifac, pred, scores);
}

// round 9
// speedup vs baseline: 1.0231x; 1.0231x over previous
#include <cuda_runtime.h>
#include <cstdint>

#define PP     8       // personas
#define FF     64      // factor dim
#define SB     200     // items per batch row
#define TPB    256
#define VPITCH 272     // 17 x 16B: odd pitch -> conflict-free LDS.128
#define U_OFF  (SB * VPITCH)        // 54400
#define SMEMB  (U_OFF + PP*FF*4)    // 56448 B -> 4 CTAs/SM
#define TXB    (SB * FF * 4 + PP * FF * 4)   // 53248 expected tx bytes

typedef unsigned long long ull;

__device__ __forceinline__ ull fma2(ull a, ull b, ull c) {
    ull d; asm("fma.rn.f32x2 %0, %1, %2, %3;" : "=l"(d) : "l"(a), "l"(b), "l"(c)); return d;
}
__device__ __forceinline__ void lds16(ull& a, ull& b, uint32_t addr) {
    asm volatile("ld.shared.v2.b64 {%0,%1}, [%2];" : "=l"(a), "=l"(b) : "r"(addr));
}
__device__ __forceinline__ float hsum2(ull a) {
    return __uint_as_float((unsigned)a) + __uint_as_float((unsigned)(a >> 32));
}
// bulk gmem->smem copy via TMA/DMA engine (off the LSU path)
__device__ __forceinline__ void bulk_cp(uint32_t dst, const void* src, uint32_t bytes, uint32_t mbar) {
    asm volatile("cp.async.bulk.shared::cta.global.mbarrier::complete_tx::bytes [%0], [%1], %2, [%3];"
                 :: "r"(dst), "l"(src), "r"(bytes), "r"(mbar) : "memory");
}
__device__ __forceinline__ void mbar_wait(uint32_t addr) {
    asm volatile(
        "{\n\t"
        ".reg .pred P;\n\t"
        "LAB_%=:\n\t"
        "mbarrier.try_wait.parity.acquire.cta.shared::cta.b64 P, [%0], 0, 0x989680;\n\t"
        "@!P bra LAB_%=;\n\t"
        "}\n\t"
        :: "r"(addr) : "memory");
}

__global__ __launch_bounds__(TPB, 4) void cf_kernel(
    const int*   __restrict__ user,     // [B]
    const int*   __restrict__ items,    // [B,SB]
    const float* __restrict__ ufac,     // [N_USERS, PP, FF]
    const float* __restrict__ ifac,     // [N_ITEMS, FF]
    float*       __restrict__ pred,     // [B,SB]
    float*       __restrict__ scores)   // [B,SB,PP]
{
    extern __shared__ __align__(16) char smem[];
    __shared__ __align__(8) ull mbar;

    const int tid = threadIdx.x;
    const long long b = blockIdx.x;

    const uint32_t sv = (uint32_t)__cvta_generic_to_shared(smem);
    const uint32_t su = sv + U_OFF;
    const uint32_t mb = (uint32_t)__cvta_generic_to_shared(&mbar);

    if (tid == 0)
        asm volatile("mbarrier.init.shared.b64 [%0], 1;" :: "r"(mb) : "memory");
    __syncthreads();

    // ---- Gather via TMA bulk: one 256B copy per item row + one 2KB copy for u ----
    if (tid == 0)
        asm volatile("mbarrier.arrive.expect_tx.shared.b64 _, [%0], %1;" :: "r"(mb), "r"(TXB) : "memory");
    if (tid < SB) {
        const int idx = __ldg(items + b * SB + tid);
        bulk_cp(sv + (uint32_t)(tid * VPITCH), ifac + (long long)idx * FF, FF * 4, mb);
    } else if (tid == SB) {
        const float* ubp = ufac + (long long)__ldg(&user[b]) * (PP * FF);
        bulk_cp(su, ubp, PP * FF * 4, mb);
    }

    // ---- Compute: pair (2k,2k+1) shares rows (k, k+100); each does 4 personas ----
    if (tid < 200) {
        mbar_wait(mb);

        const int pair = tid >> 1;   // 0..99
        const int half = tid & 1;    // persona half
        const uint32_t v0a = sv + (uint32_t)(pair * VPITCH);
        const uint32_t v1a = v0a + 100u * VPITCH;
        const uint32_t ua  = su + (uint32_t)(half * 4 * 256);

        ull acc0[4], acc1[4];
        #pragma unroll
        for (int p = 0; p < 4; p++) { acc0[p] = 0ull; acc1[p] = 0ull; }

        #pragma unroll
        for (int cc = 0; cc < FF / 4; cc++) {
            ull v0x, v0y, v1x, v1y;
            lds16(v0x, v0y, v0a + cc * 16);   // pair lanes same addr -> merged
            lds16(v1x, v1y, v1a + cc * 16);
            #pragma unroll
            for (int p = 0; p < 4; p++) {
                ull ux, uy;
                lds16(ux, uy, ua + p * 256 + cc * 16);  // broadcast (2 addrs/warp)
                acc0[p] = fma2(v0x, ux, acc0[p]);
                acc0[p] = fma2(v0y, uy, acc0[p]);
                acc1[p] = fma2(v1x, ux, acc1[p]);
                acc1[p] = fma2(v1y, uy, acc1[p]);
            }
        }

        const unsigned msk = __activemask();
        #pragma unroll
        for (int j = 0; j < 2; j++) {
            const ull* accp = (j == 0) ? acc0 : acc1;
            float mine[4];
            #pragma unroll
            for (int p = 0; p < 4; p++) mine[p] = hsum2(accp[p]);

            float oth[4];
            #pragma unroll
            for (int p = 0; p < 4; p++) oth[p] = __shfl_xor_sync(msk, mine[p], 1);

            float r[PP];
            #pragma unroll
            for (int p = 0; p < 4; p++) {
                r[half * 4 + p]       = mine[p];
                r[(1 - half) * 4 + p] = oth[p];
            }

            float m = r[0];
            #pragma unroll
            for (int p = 1; p < PP; p++) m = fmaxf(m, r[p]);
            float e[PP], sum = 0.f;
            #pragma unroll
            for (int p = 0; p < PP; p++) { e[p] = __expf(r[p] - m); sum += e[p]; }
            const float inv = 1.f / sum;

            float a[PP], pr = 0.f;
            #pragma unroll
            for (int p = 0; p < PP; p++) { a[p] = e[p] * inv; pr = fmaf(a[p], r[p], pr); }

            const int s = pair + 100 * j;
            const long long g = b * SB + s;
            if (half == 0) pred[g] = pr;
            *(float4*)(scores + g * (long long)PP + half * 4) =
                make_float4(a[half * 4], a[half * 4 + 1], a[half * 4 + 2], a[half * 4 + 3]);
        }
    }
}

extern "C" void kernel_launch(void* const* d_in, const int* in_sizes, int n_in,
                              void* d_out, int out_size) {
    const int*   user  = (const int*)d_in[0];
    const int*   items = (const int*)d_in[1];
    const float* ufac  = (const float*)d_in[2];
    const float* ifac  = (const float*)d_in[3];

    const int B = in_sizes[0];

    float* out    = (float*)d_out;
    float* pred   = out;                        // [B,SB]
    float* scores = out + (long long)B * SB;    // [B,SB,PP]

    cudaFuncSetAttribute(cf_kernel, cudaFuncAttributeMaxDynamicSharedMemorySize, SMEMB);

    cf_kernel<<<B, TPB, SMEMB>>>(user, items, ufac, ifac, pred, scores);
}